// round 10
// baseline (speedup 1.0000x reference)
#include <cuda_runtime.h>
#include <cuda_fp16.h>
#include <cstdint>

// ---------------- problem constants ----------------
constexpr int B_   = 2;
constexpr int C_   = 256;
constexpr int Hh   = 48;
constexpr int Ww   = 48;
constexpr int H3   = 144;            // sampled grid
constexpr int HO   = 142, WO = 142;
constexpr int NPB  = HO * WO;        // 20164
constexpr int NQ   = NPB / 4;        // 5041
constexpr int NA   = 5;

// Winograd F(2,3) along v: 4 components, K = C*3 (ki taps)
constexpr int KW   = C_ * 3;         // 768
constexpr int VW   = 72;             // V row width (71 valid tiles + 1 pad)
constexpr int PLV  = H3 * VW;        // 10368 per (comp, ab, ci) plane
constexpr size_t CPSTR = (size_t)NA * B_ * C_ * PLV;   // comp stride: 26,542,080
constexpr int TN2  = HO * VW;        // 10224 valid n' per (a,b)
constexpr int PADE = 8192;

// conv-GEMM tiling: 64co x 64n' x 4 comps per CTA
constexpr int CH2   = 64;            // k per chunk (4 ksteps of 16)
constexpr int NCH2  = KW / CH2;      // 12 chunks per comp
constexpr int NGCH  = 4 * NCH2;      // 48 flat chunks
constexpr int NT2   = 160;           // ceil(10224/64)
constexpr int AROW2 = 144;           // 128B payload + 16 pad
constexpr int BROW2 = 144;
constexpr int OFFB2 = 64 * AROW2;    // 9216
constexpr int STAGE2 = OFFB2 + 64 * BROW2;   // 18432
constexpr int SMEM2  = 4 * STAGE2;           // 73728

// att kernel smem
constexpr int ATT_SMEM = (8192 + 32768 + 512 + 64 + 2048) * 4;  // 174336

// ---------------- static scratch ----------------
__device__ __align__(16) unsigned short g_v[4 * CPSTR + PADE];   // fp16 V components (~212 MB)
__device__ __align__(16) unsigned short g_wU[4 * C_ * KW];       // fp16 transformed weights
__device__ __align__(16) __half g_y0H[B_ * C_ * NPB];
__device__ __align__(16) __half g_feasH[4 * B_ * C_ * NPB];
__device__ float g_fsum[B_ * C_];
__device__ float g_att[B_ * 4 * C_];

// ---------------- angle offset tables ----------------
#define S2  1.4142135623730951
#define S2H 0.7071067811865476
__constant__ float c_ox[45] = {
    0.f,0.f,0.f,0.f,0.f,0.f,0.f,0.f,0.f,
    (float)(1.0-S2), (float)(1.0-S2H), 1.f, (float)(-S2H), 0.f, (float)(S2H),
    -1.f, (float)(S2H-1.0), (float)(S2-1.0),
    0.f,1.f,2.f,-1.f,0.f,1.f,-2.f,-1.f,0.f,
    1.f, (float)(1.0+S2H), (float)(1.0+S2), (float)(-S2H), 0.f, (float)(S2H),
    (float)(-1.0-S2), (float)(-1.0-S2H), -1.f,
    2.f,2.f,2.f,0.f,0.f,0.f,-2.f,-2.f,-2.f
};
__constant__ float c_oy[45] = {
    0.f,0.f,0.f,0.f,0.f,0.f,0.f,0.f,0.f,
    1.f, (float)(S2H), (float)(S2-1.0), (float)(1.0-S2H), 0.f, (float)(S2H-1.0),
    (float)(1.0-S2), (float)(-S2H), -1.f,
    2.f,1.f,0.f,1.f,0.f,-1.f,0.f,-1.f,-2.f,
    (float)(1.0+S2), (float)(S2H), -1.f, (float)(1.0+S2H), 0.f, (float)(-1.0-S2H),
    1.f, (float)(-S2H), (float)(1.0+S2),
    2.f,0.f,-2.f,2.f,0.f,-2.f,2.f,0.f,-2.f
};
__constant__ int c_oxi[27] = {
    0,0,0,0,0,0,0,0,0,
    0,1,2,-1,0,1,-2,-1,0,
    2,2,2,0,0,0,-2,-2,-2
};
__constant__ int c_oyi[27] = {
    0,0,0,0,0,0,0,0,0,
    2,1,0,1,0,-1,0,-1,-2,
    2,0,-2,2,0,-2,2,0,-2
};

// ---------------- helpers ----------------
__device__ __forceinline__ uint32_t smem_u32(const void* p) {
    uint32_t a;
    asm("{ .reg .u64 t; cvta.to.shared.u64 t, %1; cvt.u32.u64 %0, t; }" : "=r"(a) : "l"(p));
    return a;
}
__device__ __forceinline__ void cpasync16(uint32_t dst, const void* src) {
    asm volatile("cp.async.cg.shared.global [%0], [%1], 16;" :: "r"(dst), "l"(src));
}
__device__ __forceinline__ void cp_commit() {
    asm volatile("cp.async.commit_group;" ::: "memory");
}
__device__ __forceinline__ void cp_wait2() {
    asm volatile("cp.async.wait_group %0;" :: "n"(2) : "memory");
}
__device__ __forceinline__ void ldmx4(uint32_t* r, uint32_t addr) {
    asm volatile("ldmatrix.sync.aligned.m8n8.x4.shared.b16 {%0,%1,%2,%3}, [%4];"
                 : "=r"(r[0]), "=r"(r[1]), "=r"(r[2]), "=r"(r[3]) : "r"(addr));
}
__device__ __forceinline__ void ldmx4t(uint32_t* r, uint32_t addr) {
    asm volatile("ldmatrix.sync.aligned.m8n8.x4.trans.shared.b16 {%0,%1,%2,%3}, [%4];"
                 : "=r"(r[0]), "=r"(r[1]), "=r"(r[2]), "=r"(r[3]) : "r"(addr));
}
__device__ __forceinline__ void mma_fp16(float4& d, const uint32_t a[4], uint32_t b0, uint32_t b1) {
    asm volatile("mma.sync.aligned.m16n8k16.row.col.f32.f16.f16.f32 "
                 "{%0,%1,%2,%3}, {%4,%5,%6,%7}, {%8,%9}, {%0,%1,%2,%3};"
                 : "+f"(d.x), "+f"(d.y), "+f"(d.z), "+f"(d.w)
                 : "r"(a[0]), "r"(a[1]), "r"(a[2]), "r"(a[3]), "r"(b0), "r"(b1));
}

// ---------------- 0) prep: weight winograd transform + fsum zero ----------------
__global__ void prep_kernel(const float* __restrict__ w) {
    int i = blockIdx.x * blockDim.x + threadIdx.x;
    if (i < B_ * C_) g_fsum[i] = 0.f;
    if (i >= C_ * KW) return;
    int co = i / KW;
    int k  = i - co * KW;          // ci*3 + ki
    int ci = k / 3, ki = k - ci * 3;
    const float* gp = w + (((size_t)co * C_ + ci) * 3 + ki) * 3;
    float g0 = gp[0], g1 = gp[1], g2 = gp[2];
    float U0 = g0;
    float U1 = 0.5f * (g0 + g1 + g2);
    float U2 = 0.5f * (g0 - g1 + g2);
    float U3 = g2;
    g_wU[(0 * C_ + co) * KW + k] = __half_as_ushort(__float2half_rn(U0));
    g_wU[(1 * C_ + co) * KW + k] = __half_as_ushort(__float2half_rn(U1));
    g_wU[(2 * C_ + co) * KW + k] = __half_as_ushort(__float2half_rn(U2));
    g_wU[(3 * C_ + co) * KW + k] = __half_as_ushort(__float2half_rn(U3));
}

// ---------------- 1) fused bilinear resample + V transform ----------------
// grid: (81, C_, NA*B_), block 64; thread handles (row r, tile-pair tp) -> tiles 2tp, 2tp+1
__global__ void sampleV_kernel(const float* __restrict__ x) {
    int ip = blockIdx.x * 64 + threadIdx.x;    // [0, 5184) = 144 * 36
    int c  = blockIdx.y;
    int ab = blockIdx.z;                        // a*2 + bb
    int a  = ab >> 1, bb = ab & 1;

    int r  = ip / 36;
    int tp = ip - r * 36;

    int i = r / 3, ki = r - i * 3;
    const float* xp = x + (bb * C_ + c) * (Hh * Ww);

    float s[6];
    int jmax = (tp == 35) ? 4 : 6;
    for (int j = 0; j < 6; j++) {
        if (j >= jmax) { s[j] = 0.f; continue; }
        int cc = 4 * tp + j;                    // sampled-plane column, < 144
        int jj = cc / 3, kj = cc - jj * 3;
        int k9 = ki * 3 + kj;
        float v;
        if ((a & 1) == 0) {
            int ia = a >> 1;
            int px = i + ki + c_oxi[ia * 9 + k9];
            int py = jj + kj + c_oyi[ia * 9 + k9];
            v = (px >= 1 && px <= Hh && py >= 1 && py <= Ww)
                ? xp[(px - 1) * Ww + (py - 1)] : 0.f;
        } else {
            float sx = (float)(ki - 1) + c_ox[a * 9 + k9];
            float sy = (float)(kj - 1) + c_oy[a * 9 + k9];
            float px = (float)(i + 1) + sx;
            float py = (float)(jj + 1) + sy;
            float fx = floorf(px), fy = floorf(py);
            const float HI = 49.f;
            float ltx = fminf(fmaxf(fx,       0.f), HI);
            float lty = fminf(fmaxf(fy,       0.f), HI);
            float rbx = fminf(fmaxf(fx + 1.f, 0.f), HI);
            float rby = fminf(fmaxf(fy + 1.f, 0.f), HI);
            float pxc = fminf(fmaxf(px,       0.f), HI);
            float pyc = fminf(fmaxf(py,       0.f), HI);
            float g_lt = (1.f + (ltx - pxc)) * (1.f + (lty - pyc));
            float g_rb = (1.f - (rbx - pxc)) * (1.f - (rby - pyc));
            float g_lb = (1.f + (ltx - pxc)) * (1.f - (rby - pyc));
            float g_rt = (1.f - (rbx - pxc)) * (1.f + (lty - pyc));
            int ix0 = (int)ltx, iy0 = (int)lty, ix1 = (int)rbx, iy1 = (int)rby;
            auto gat = [&](int ix, int iy) -> float {
                ix -= 1; iy -= 1;
                if (ix < 0 || ix >= Hh || iy < 0 || iy >= Ww) return 0.f;
                return xp[ix * Ww + iy];
            };
            v = g_lt * gat(ix0, iy0) + g_rb * gat(ix1, iy1)
              + g_lb * gat(ix0, iy1) + g_rt * gat(ix1, iy0);
        }
        s[j] = v;
    }

    // V = B^T d per tile: [d0-d2, d1+d2, d2-d1, d1-d3]
    float v0[4] = { s[0] - s[2], s[1] + s[2], s[2] - s[1], s[1] - s[3] };
    float v1[4];
    if (tp == 35) { v1[0] = v1[1] = v1[2] = v1[3] = 0.f; }
    else {
        v1[0] = s[2] - s[4]; v1[1] = s[3] + s[4];
        v1[2] = s[4] - s[3]; v1[3] = s[3] - s[5];
    }

    size_t base = ((size_t)ab * C_ + c) * PLV + r * VW + 2 * tp;
#pragma unroll
    for (int cp = 0; cp < 4; cp++) {
        uint32_t pk = (uint32_t)__half_as_ushort(__float2half_rn(v0[cp]))
                    | ((uint32_t)__half_as_ushort(__float2half_rn(v1[cp])) << 16);
        *(uint32_t*)&g_v[(size_t)cp * CPSTR + base] = pk;
    }
}

// ---------------- 2) winograd GEMMs (4 comps) + A^T + BN/ReLU + GAP ----------------
__global__ void __launch_bounds__(256, 2)
conv_wino_kernel(const float* __restrict__ gma, const float* __restrict__ bta,
                 const float* __restrict__ mu,  const float* __restrict__ var) {
    extern __shared__ char smem[];
    const uint32_t sb = smem_u32(smem);
    const int tid = threadIdx.x;
    const int a   = blockIdx.z;
    const int bb  = blockIdx.y;
    const int ab  = a * 2 + bb;
    const int coBase = (blockIdx.x & 3) * 64;
    const int nOff   = (blockIdx.x >> 2) * 64;   // n' = u*72 + t
    const int lane = tid & 31, wid = tid >> 5;
    const int wm = wid & 1, wn = wid >> 1;       // warp tile: 32m @ wm*32, 16n @ wn*16

    // fill mapping: 64 rows x 8 pieces, 2 pieces/thread
    const int frow = tid >> 2, fpc = tid & 3;

    auto issueG = [&](int gch) {
        int cp = gch / NCH2;
        int ch = gch - cp * NCH2;
        const uint32_t sg = sb + (uint32_t)(gch & 3) * STAGE2;
        // A: transformed weights
        {
            const char* src = (const char*)g_wU
                + ((size_t)(cp * C_ + coBase + frow) * KW + ch * CH2) * 2;
            uint32_t dst = sg + frow * AROW2;
            cpasync16(dst + fpc * 16,       src + fpc * 16);
            cpasync16(dst + (fpc + 4) * 16, src + (fpc + 4) * 16);
        }
        // B: V component plane, row k=(ci,ki) -> contiguous 64 n'
        {
            int k  = ch * CH2 + frow;
            int ci = k / 3;
            int ki = k - ci * 3;
            const char* src = (const char*)g_v
                + ((size_t)cp * CPSTR + ((size_t)ab * C_ + ci) * PLV + ki * VW + nOff) * 2;
            uint32_t dst = sg + OFFB2 + frow * BROW2;
            cpasync16(dst + fpc * 16,       src + fpc * 16);
            cpasync16(dst + (fpc + 4) * 16, src + (fpc + 4) * 16);
        }
    };

    float4 acc[4][2][2];
#pragma unroll
    for (int cp = 0; cp < 4; cp++)
#pragma unroll
        for (int mt = 0; mt < 2; mt++)
#pragma unroll
            for (int nf = 0; nf < 2; nf++)
                acc[cp][mt][nf] = make_float4(0.f, 0.f, 0.f, 0.f);

    const uint32_t aLd = (uint32_t)(wm * 32 + (lane & 15)) * AROW2 + (uint32_t)(lane >> 4) * 16;
    const uint32_t bLd = (uint32_t)(lane & 15) * BROW2
                       + (uint32_t)(wn * 16 + (lane >> 4) * 8) * 2;

    auto computeStage = [&](int st, float4 (&ac)[2][2]) {
        const uint32_t sg = sb + (uint32_t)st * STAGE2;
#pragma unroll
        for (int ks = 0; ks < 4; ks++) {
            uint32_t aH[2][4], bV[4];
            ldmx4(aH[0], sg + aLd + ks * 32);
            ldmx4(aH[1], sg + aLd + 16 * AROW2 + ks * 32);
            ldmx4t(bV, sg + OFFB2 + bLd + (uint32_t)(ks * 16) * BROW2);
#pragma unroll
            for (int mt = 0; mt < 2; mt++) {
                mma_fp16(ac[mt][0], aH[mt], bV[0], bV[1]);
                mma_fp16(ac[mt][1], aH[mt], bV[2], bV[3]);
            }
        }
    };

    // prologue: 3 stages
#pragma unroll
    for (int s = 0; s < 3; s++) { issueG(s); cp_commit(); }

    // flat pipeline across comps; acc index static via unrolled comp loop
#pragma unroll
    for (int cp = 0; cp < 4; cp++) {
        for (int ch = 0; ch < NCH2; ch++) {
            int gch = cp * NCH2 + ch;
            cp_wait2();
            __syncthreads();
            if (gch + 3 < NGCH) issueG(gch + 3);
            cp_commit();
            computeStage(gch & 3, acc[cp]);
        }
    }

    // ---- epilogue: A^T, BN+ReLU, fp16 half2 stores, fused GAP ----
    auto emit = [&](int co, int np, float M0, float M1, float M2, float M3,
                    float sc, float sh, float& ss) {
        if (np >= TN2) return;
        int u = np / VW, t = np - u * VW;
        if (t >= 71) return;
        int p = u * WO + 2 * t;
        float o0 = M0 + M1 + M2;
        float o1 = M1 - M2 - M3;
        if (a == 0) {
            *(__half2*)&g_y0H[((size_t)(bb * C_ + co)) * NPB + p] = __floats2half2_rn(o0, o1);
        } else {
            float f0 = fmaxf(fmaf(o0, sc, sh), 0.f);
            float f1 = fmaxf(fmaf(o1, sc, sh), 0.f);
            *(__half2*)&g_feasH[(((size_t)(a - 1) * B_ + bb) * C_ + co) * NPB + p] =
                __floats2half2_rn(f0, f1);
            ss += f0 + f1;
        }
    };

#pragma unroll
    for (int mt = 0; mt < 2; mt++) {
        int co0 = coBase + wm * 32 + mt * 16 + (lane >> 2);
        int co1 = co0 + 8;
        float sc0 = 1.f, sh0 = 0.f, sc1 = 1.f, sh1 = 0.f;
        if (a > 0) {
            int br = a - 1;
            float vv0 = var[br * C_ + co0], vv1 = var[br * C_ + co1];
            sc0 = gma[br * C_ + co0] * rsqrtf(vv0 + 1e-5f);
            sc1 = gma[br * C_ + co1] * rsqrtf(vv1 + 1e-5f);
            sh0 = bta[br * C_ + co0] - mu[br * C_ + co0] * sc0;
            sh1 = bta[br * C_ + co1] - mu[br * C_ + co1] * sc1;
        }
        float s0 = 0.f, s1 = 0.f;
#pragma unroll
        for (int nf = 0; nf < 2; nf++) {
            float4 m0 = acc[0][mt][nf], m1 = acc[1][mt][nf];
            float4 m2 = acc[2][mt][nf], m3 = acc[3][mt][nf];
            int n0 = nOff + wn * 16 + nf * 8 + (lane & 3) * 2;
            emit(co0, n0,     m0.x, m1.x, m2.x, m3.x, sc0, sh0, s0);
            emit(co0, n0 + 1, m0.y, m1.y, m2.y, m3.y, sc0, sh0, s0);
            emit(co1, n0,     m0.z, m1.z, m2.z, m3.z, sc1, sh1, s1);
            emit(co1, n0 + 1, m0.w, m1.w, m2.w, m3.w, sc1, sh1, s1);
        }
        if (a > 0) {
            s0 += __shfl_xor_sync(0xffffffffu, s0, 1);
            s0 += __shfl_xor_sync(0xffffffffu, s0, 2);
            s1 += __shfl_xor_sync(0xffffffffu, s1, 1);
            s1 += __shfl_xor_sync(0xffffffffu, s1, 2);
            if ((lane & 3) == 0) {
                atomicAdd(&g_fsum[bb * C_ + co0], s0);
                atomicAdd(&g_fsum[bb * C_ + co1], s1);
            }
        }
    }
}

// ---------------- 3) attention: smem-staged weights, 1024 threads ----------------
__global__ void __launch_bounds__(1024)
att_kernel(const float* __restrict__ fc1w, const float* __restrict__ fc1b,
           const float* __restrict__ fc2w, const float* __restrict__ fc2b) {
    extern __shared__ float sm[];
    float* sW1  = sm;                  // [32*256]
    float* sW2  = sm + 8192;           // [32][1024] transposed: sW2[d*1024 + (m*C+c)]
    float* sFs  = sm + 8192 + 32768;   // [512]
    float* sZ   = sFs + 512;           // [64]
    float* sAtt = sZ + 64;             // [2048]
    int t = threadIdx.x;

#pragma unroll
    for (int i = 0; i < 2; i++)
        ((float4*)sW1)[t + i * 1024] = ((const float4*)fc1w)[t + i * 1024];
#pragma unroll
    for (int i = 0; i < 8; i++) {
        int v4 = t + i * 1024;
        float4 w4 = ((const float4*)fc2w)[v4];
        int mc = v4 >> 3;
        int d0 = (v4 & 7) * 4;
        sW2[(d0 + 0) * 1024 + mc] = w4.x;
        sW2[(d0 + 1) * 1024 + mc] = w4.y;
        sW2[(d0 + 2) * 1024 + mc] = w4.z;
        sW2[(d0 + 3) * 1024 + mc] = w4.w;
    }
    if (t < B_ * C_) sFs[t] = g_fsum[t] * (1.f / (float)NPB);
    __syncthreads();

    {
        int pair = t >> 4;
        int b = pair >> 5, d = pair & 31;
        int sl = t & 15;
        float s = 0.f;
#pragma unroll
        for (int c = sl; c < C_; c += 16) s += sFs[b * C_ + c] * sW1[d * C_ + c];
        s += __shfl_down_sync(0xffffffffu, s, 8, 16);
        s += __shfl_down_sync(0xffffffffu, s, 4, 16);
        s += __shfl_down_sync(0xffffffffu, s, 2, 16);
        s += __shfl_down_sync(0xffffffffu, s, 1, 16);
        if (sl == 0) sZ[b * 32 + d] = s + fc1b[d];
    }
    __syncthreads();

#pragma unroll
    for (int i = 0; i < 2; i++) {
        int o = t + i * 1024;
        int b = o >> 10;
        int mc = o & 1023;
        float s = fc2b[mc];
#pragma unroll
        for (int d = 0; d < 32; d++) s += sZ[b * 32 + d] * sW2[d * 1024 + mc];
        sAtt[b * 1024 + mc] = s;
    }
    __syncthreads();

    if (t < B_ * C_) {
        int b = t >> 8, c = t & 255;
        float a0 = sAtt[b * 1024 + 0 * C_ + c];
        float a1 = sAtt[b * 1024 + 1 * C_ + c];
        float a2 = sAtt[b * 1024 + 2 * C_ + c];
        float a3 = sAtt[b * 1024 + 3 * C_ + c];
        float mx = fmaxf(fmaxf(a0, a1), fmaxf(a2, a3));
        float e0 = expf(a0 - mx), e1 = expf(a1 - mx), e2 = expf(a2 - mx), e3 = expf(a3 - mx);
        float inv = 1.f / (e0 + e1 + e2 + e3);
        g_att[(b * 4 + 0) * C_ + c] = e0 * inv;
        g_att[(b * 4 + 1) * C_ + c] = e1 * inv;
        g_att[(b * 4 + 2) * C_ + c] = e2 * inv;
        g_att[(b * 4 + 3) * C_ + c] = e3 * inv;
    }
}

// ---------------- 4) final blend ----------------
__global__ void final_kernel(float* __restrict__ out) {
    int idx = blockIdx.x * blockDim.x + threadIdx.x;
    const int total = B_ * C_ * NQ;
    if (idx >= total) return;
    int pq = idx % NQ;
    int bc = idx / NQ;
    int c  = bc % C_, b = bc / C_;

    uint2 yv = ((const uint2*)&g_y0H[(size_t)bc * NPB])[pq];
    float2 ylo = __half22float2(*(__half2*)&yv.x);
    float2 yhi = __half22float2(*(__half2*)&yv.y);
    float4 o = make_float4(ylo.x, ylo.y, yhi.x, yhi.y);
#pragma unroll
    for (int m = 0; m < 4; m++) {
        float wm = g_att[(b * 4 + m) * C_ + c];
        uint2 fv = ((const uint2*)&g_feasH[((size_t)m * B_ * C_ + bc) * NPB])[pq];
        float2 lo = __half22float2(*(__half2*)&fv.x);
        float2 hi = __half22float2(*(__half2*)&fv.y);
        o.x = fmaf(lo.x, wm, o.x);
        o.y = fmaf(lo.y, wm, o.y);
        o.z = fmaf(hi.x, wm, o.z);
        o.w = fmaf(hi.y, wm, o.w);
    }
    ((float4*)out)[idx] = o;
}

// ---------------- launch ----------------
extern "C" void kernel_launch(void* const* d_in, const int* in_sizes, int n_in,
                              void* d_out, int out_size) {
    const float* x    = (const float*)d_in[0];
    const float* w    = (const float*)d_in[1];
    const float* gma  = (const float*)d_in[2];
    const float* bta  = (const float*)d_in[3];
    const float* mu   = (const float*)d_in[4];
    const float* var  = (const float*)d_in[5];
    const float* fc1w = (const float*)d_in[6];
    const float* fc1b = (const float*)d_in[7];
    const float* fc2w = (const float*)d_in[8];
    const float* fc2b = (const float*)d_in[9];
    float* out = (float*)d_out;

    cudaFuncSetAttribute(conv_wino_kernel,
                         cudaFuncAttributeMaxDynamicSharedMemorySize, SMEM2);
    cudaFuncSetAttribute(att_kernel,
                         cudaFuncAttributeMaxDynamicSharedMemorySize, ATT_SMEM);

    prep_kernel<<<(C_ * KW + 255) / 256, 256>>>(w);

    dim3 sgrid(81, C_, NA * B_);
    sampleV_kernel<<<sgrid, 64>>>(x);

    dim3 grid(4 * NT2, B_, NA);
    conv_wino_kernel<<<grid, 256, SMEM2>>>(gma, bta, mu, var);

    att_kernel<<<1, 1024, ATT_SMEM>>>(fc1w, fc1b, fc2w, fc2b);
    final_kernel<<<(B_ * C_ * NQ + 255) / 256, 256>>>(out);
}

// round 11
// speedup vs baseline: 1.2423x; 1.2423x over previous
#include <cuda_runtime.h>
#include <cuda_fp16.h>
#include <cstdint>

// ---------------- problem constants ----------------
constexpr int B_   = 2;
constexpr int C_   = 256;
constexpr int Hh   = 48;
constexpr int Ww   = 48;
constexpr int H3   = 144;
constexpr int HO   = 142, WO = 142;
constexpr int NPB  = HO * WO;        // 20164
constexpr int NQ   = NPB / 4;        // 5041
constexpr int NA   = 5;

// Winograd F(2,3) along v: 4 components, K = C*3
constexpr int KW   = C_ * 3;         // 768
constexpr int VW   = 72;             // V row width (71 valid tiles + 1 pad)
constexpr int PLV  = H3 * VW;        // 10368
constexpr size_t CPSTR = (size_t)NA * B_ * C_ * PLV;   // 26,542,080
constexpr int PADE = 8192;

// GEMM tiling (r9-proven shape): 128co x 128n, CHUNK 32, 4 stages
constexpr int NPAD  = 10240;         // padded N per (ab): 80 tiles * 128
constexpr int NT    = 80;
constexpr int CHUNK = 32;
constexpr int NCH   = KW / CHUNK;    // 24
constexpr int NS    = 4;
constexpr int AROWB = 80;
constexpr int BROWB = 272;
constexpr int OFF_B = 128 * AROWB;                 // 10240
constexpr int STAGE = OFF_B + 32 * BROWB;          // 18944
constexpr int SMEM_TOTAL = NS * STAGE;             // 75776

constexpr int ATT_SMEM = (8192 + 32768 + 512 + 64 + 2048) * 4;  // 174336

// ---------------- static scratch ----------------
__device__ __align__(16) unsigned short g_v[4 * CPSTR + PADE];   // fp16 V components
__device__ __align__(16) unsigned short g_wU[4 * C_ * KW];       // fp16 transformed weights
__device__ __align__(16) __half g_M[(size_t)4 * NA * B_ * C_ * NPAD];  // raw GEMM outputs
__device__ __align__(16) __half g_y0H[B_ * C_ * NPB];
__device__ __align__(16) __half g_feasH[4 * B_ * C_ * NPB];
__device__ float g_fsum[B_ * C_];
__device__ float g_att[B_ * 4 * C_];

// ---------------- angle offset tables ----------------
#define S2  1.4142135623730951
#define S2H 0.7071067811865476
__constant__ float c_ox[45] = {
    0.f,0.f,0.f,0.f,0.f,0.f,0.f,0.f,0.f,
    (float)(1.0-S2), (float)(1.0-S2H), 1.f, (float)(-S2H), 0.f, (float)(S2H),
    -1.f, (float)(S2H-1.0), (float)(S2-1.0),
    0.f,1.f,2.f,-1.f,0.f,1.f,-2.f,-1.f,0.f,
    1.f, (float)(1.0+S2H), (float)(1.0+S2), (float)(-S2H), 0.f, (float)(S2H),
    (float)(-1.0-S2), (float)(-1.0-S2H), -1.f,
    2.f,2.f,2.f,0.f,0.f,0.f,-2.f,-2.f,-2.f
};
__constant__ float c_oy[45] = {
    0.f,0.f,0.f,0.f,0.f,0.f,0.f,0.f,0.f,
    1.f, (float)(S2H), (float)(S2-1.0), (float)(1.0-S2H), 0.f, (float)(S2H-1.0),
    (float)(1.0-S2), (float)(-S2H), -1.f,
    2.f,1.f,0.f,1.f,0.f,-1.f,0.f,-1.f,-2.f,
    (float)(1.0+S2), (float)(S2H), -1.f, (float)(1.0+S2H), 0.f, (float)(-1.0-S2H),
    1.f, (float)(-S2H), (float)(1.0+S2),
    2.f,0.f,-2.f,2.f,0.f,-2.f,2.f,0.f,-2.f
};
__constant__ int c_oxi[27] = {
    0,0,0,0,0,0,0,0,0,
    0,1,2,-1,0,1,-2,-1,0,
    2,2,2,0,0,0,-2,-2,-2
};
__constant__ int c_oyi[27] = {
    0,0,0,0,0,0,0,0,0,
    2,1,0,1,0,-1,0,-1,-2,
    2,0,-2,2,0,-2,2,0,-2
};

// ---------------- helpers ----------------
__device__ __forceinline__ uint32_t smem_u32(const void* p) {
    uint32_t a;
    asm("{ .reg .u64 t; cvta.to.shared.u64 t, %1; cvt.u32.u64 %0, t; }" : "=r"(a) : "l"(p));
    return a;
}
__device__ __forceinline__ void cpasync16(uint32_t dst, const void* src) {
    asm volatile("cp.async.cg.shared.global [%0], [%1], 16;" :: "r"(dst), "l"(src));
}
__device__ __forceinline__ void cp_commit() {
    asm volatile("cp.async.commit_group;" ::: "memory");
}
__device__ __forceinline__ void cp_wait2() {
    asm volatile("cp.async.wait_group %0;" :: "n"(2) : "memory");
}
__device__ __forceinline__ void ldmx4(uint32_t* r, uint32_t addr) {
    asm volatile("ldmatrix.sync.aligned.m8n8.x4.shared.b16 {%0,%1,%2,%3}, [%4];"
                 : "=r"(r[0]), "=r"(r[1]), "=r"(r[2]), "=r"(r[3]) : "r"(addr));
}
__device__ __forceinline__ void ldmx4t(uint32_t* r, uint32_t addr) {
    asm volatile("ldmatrix.sync.aligned.m8n8.x4.trans.shared.b16 {%0,%1,%2,%3}, [%4];"
                 : "=r"(r[0]), "=r"(r[1]), "=r"(r[2]), "=r"(r[3]) : "r"(addr));
}
__device__ __forceinline__ void mma_fp16(float4& d, const uint32_t a[4], uint32_t b0, uint32_t b1) {
    asm volatile("mma.sync.aligned.m16n8k16.row.col.f32.f16.f16.f32 "
                 "{%0,%1,%2,%3}, {%4,%5,%6,%7}, {%8,%9}, {%0,%1,%2,%3};"
                 : "+f"(d.x), "+f"(d.y), "+f"(d.z), "+f"(d.w)
                 : "r"(a[0]), "r"(a[1]), "r"(a[2]), "r"(a[3]), "r"(b0), "r"(b1));
}

// ---------------- 0) prep: weight winograd transform + fsum zero ----------------
__global__ void prep_kernel(const float* __restrict__ w) {
    int i = blockIdx.x * blockDim.x + threadIdx.x;
    if (i < B_ * C_) g_fsum[i] = 0.f;
    if (i >= C_ * KW) return;
    int co = i / KW;
    int k  = i - co * KW;          // ci*3 + ki
    int ci = k / 3, ki = k - ci * 3;
    const float* gp = w + (((size_t)co * C_ + ci) * 3 + ki) * 3;
    float g0 = gp[0], g1 = gp[1], g2 = gp[2];
    float U0 = g0;
    float U1 = 0.5f * (g0 + g1 + g2);
    float U2 = 0.5f * (g0 - g1 + g2);
    float U3 = g2;
    g_wU[(0 * C_ + co) * KW + k] = __half_as_ushort(__float2half_rn(U0));
    g_wU[(1 * C_ + co) * KW + k] = __half_as_ushort(__float2half_rn(U1));
    g_wU[(2 * C_ + co) * KW + k] = __half_as_ushort(__float2half_rn(U2));
    g_wU[(3 * C_ + co) * KW + k] = __half_as_ushort(__float2half_rn(U3));
}

// ---------------- 1) fused bilinear resample + V transform ----------------
__global__ void sampleV_kernel(const float* __restrict__ x) {
    int ip = blockIdx.x * 64 + threadIdx.x;    // [0, 5184) = 144 rows * 36 tile-pairs
    int c  = blockIdx.y;
    int ab = blockIdx.z;                        // a*2 + bb
    int a  = ab >> 1, bb = ab & 1;

    int r  = ip / 36;
    int tp = ip - r * 36;

    int i = r / 3, ki = r - i * 3;
    const float* xp = x + (bb * C_ + c) * (Hh * Ww);

    float s[6];
    int jmax = (tp == 35) ? 4 : 6;
    for (int j = 0; j < 6; j++) {
        if (j >= jmax) { s[j] = 0.f; continue; }
        int cc = 4 * tp + j;
        int jj = cc / 3, kj = cc - jj * 3;
        int k9 = ki * 3 + kj;
        float v;
        if ((a & 1) == 0) {
            int ia = a >> 1;
            int px = i + ki + c_oxi[ia * 9 + k9];
            int py = jj + kj + c_oyi[ia * 9 + k9];
            v = (px >= 1 && px <= Hh && py >= 1 && py <= Ww)
                ? xp[(px - 1) * Ww + (py - 1)] : 0.f;
        } else {
            float sx = (float)(ki - 1) + c_ox[a * 9 + k9];
            float sy = (float)(kj - 1) + c_oy[a * 9 + k9];
            float px = (float)(i + 1) + sx;
            float py = (float)(jj + 1) + sy;
            float fx = floorf(px), fy = floorf(py);
            const float HI = 49.f;
            float ltx = fminf(fmaxf(fx,       0.f), HI);
            float lty = fminf(fmaxf(fy,       0.f), HI);
            float rbx = fminf(fmaxf(fx + 1.f, 0.f), HI);
            float rby = fminf(fmaxf(fy + 1.f, 0.f), HI);
            float pxc = fminf(fmaxf(px,       0.f), HI);
            float pyc = fminf(fmaxf(py,       0.f), HI);
            float g_lt = (1.f + (ltx - pxc)) * (1.f + (lty - pyc));
            float g_rb = (1.f - (rbx - pxc)) * (1.f - (rby - pyc));
            float g_lb = (1.f + (ltx - pxc)) * (1.f - (rby - pyc));
            float g_rt = (1.f - (rbx - pxc)) * (1.f + (lty - pyc));
            int ix0 = (int)ltx, iy0 = (int)lty, ix1 = (int)rbx, iy1 = (int)rby;
            auto gat = [&](int ix, int iy) -> float {
                ix -= 1; iy -= 1;
                if (ix < 0 || ix >= Hh || iy < 0 || iy >= Ww) return 0.f;
                return xp[ix * Ww + iy];
            };
            v = g_lt * gat(ix0, iy0) + g_rb * gat(ix1, iy1)
              + g_lb * gat(ix0, iy1) + g_rt * gat(ix1, iy0);
        }
        s[j] = v;
    }

    float v0[4] = { s[0] - s[2], s[1] + s[2], s[2] - s[1], s[1] - s[3] };
    float v1[4];
    if (tp == 35) { v1[0] = v1[1] = v1[2] = v1[3] = 0.f; }
    else {
        v1[0] = s[2] - s[4]; v1[1] = s[3] + s[4];
        v1[2] = s[4] - s[3]; v1[3] = s[3] - s[5];
    }

    size_t base = ((size_t)ab * C_ + c) * PLV + r * VW + 2 * tp;
#pragma unroll
    for (int cp = 0; cp < 4; cp++) {
        uint32_t pk = (uint32_t)__half_as_ushort(__float2half_rn(v0[cp]))
                    | ((uint32_t)__half_as_ushort(__float2half_rn(v1[cp])) << 16);
        *(uint32_t*)&g_v[(size_t)cp * CPSTR + base] = pk;
    }
}

// ---------------- 2) wino GEMM: r9 pipeline shape, one comp per blockIdx.z ----------------
__global__ void __launch_bounds__(256)
gemm_wino_kernel() {
    extern __shared__ char smem[];
    const uint32_t sb = smem_u32(smem);
    const int tid = threadIdx.x;
    const int cp  = blockIdx.z;
    const int ab  = blockIdx.y;
    const int coBase = (blockIdx.x & 1) * 128;
    const int nOff   = (blockIdx.x >> 1) * 128;
    const int lane = tid & 31, wid = tid >> 5;
    const int wm = wid & 3, wn = wid >> 2;       // warp: 32m @ wm*32, 64n @ wn*64

    const int aRow = tid >> 2, aPc = tid & 3;
    const int bRow = tid >> 4, bPc = tid & 15;

    const size_t vBase = (size_t)cp * CPSTR + (size_t)ab * C_ * PLV;

    auto issueChunk = [&](int ch, int st) {
        const uint32_t sg = sb + (uint32_t)st * STAGE;
#pragma unroll
        for (int t2 = 0; t2 < 2; t2++) {
            int row = aRow + t2 * 64;
            const char* src = (const char*)g_wU
                + ((size_t)(cp * C_ + coBase + row) * KW + (size_t)ch * CHUNK) * 2 + aPc * 16;
            cpasync16(sg + row * AROWB + aPc * 16, src);
        }
#pragma unroll
        for (int t2 = 0; t2 < 2; t2++) {
            int row = bRow + t2 * 16;
            int k  = ch * CHUNK + row;
            int ci = k / 3;
            int ki = k - ci * 3;
            const char* src = (const char*)g_v
                + (vBase + (size_t)ci * PLV + ki * VW + nOff) * 2 + bPc * 16;
            cpasync16(sg + OFF_B + row * BROWB + bPc * 16, src);
        }
    };

    float4 acc[2][8];
#pragma unroll
    for (int i = 0; i < 2; i++)
#pragma unroll
        for (int j = 0; j < 8; j++) acc[i][j] = make_float4(0.f, 0.f, 0.f, 0.f);

    const uint32_t aLd = (uint32_t)(wm * 32 + (lane & 15)) * AROWB + (uint32_t)(lane >> 4) * 16;
    const uint32_t bLd0 = (uint32_t)(lane & 15) * BROWB
                        + (uint32_t)(wn * 64 + (lane >> 4) * 8) * 2;

    auto computeStage = [&](int st) {
        const uint32_t sg = sb + (uint32_t)st * STAGE;
#pragma unroll
        for (int ks = 0; ks < 2; ks++) {
            uint32_t aH[2][4], bV[4][4];
#pragma unroll
            for (int mt = 0; mt < 2; mt++)
                ldmx4(aH[mt], sg + aLd + (uint32_t)(mt * 16) * AROWB + ks * 32);
#pragma unroll
            for (int bt = 0; bt < 4; bt++)
                ldmx4t(bV[bt], sg + OFF_B + bLd0 + (uint32_t)(ks * 16) * BROWB + (uint32_t)(bt * 16) * 2);
#pragma unroll
            for (int mt = 0; mt < 2; mt++)
#pragma unroll
                for (int nt = 0; nt < 8; nt++) {
                    uint32_t b0 = bV[nt >> 1][(nt & 1) * 2], b1 = bV[nt >> 1][(nt & 1) * 2 + 1];
                    mma_fp16(acc[mt][nt], aH[mt], b0, b1);
                }
        }
    };

#pragma unroll
    for (int s = 0; s < NS - 1; s++) { issueChunk(s, s); cp_commit(); }

    for (int ch = 0; ch < NCH; ch++) {
        cp_wait2();
        __syncthreads();
        if (ch + NS - 1 < NCH) issueChunk(ch + NS - 1, (ch + NS - 1) & (NS - 1));
        cp_commit();
        computeStage(ch & (NS - 1));
    }

    // epilogue: raw fp16 M stores (no guards: N padded to 10240 exactly)
    const int r0 = lane >> 2;
    const int cq = (lane & 3) * 2;
    __half* Mp = g_M + (size_t)(cp * NA * B_ + ab) * ((size_t)C_ * NPAD);
#pragma unroll
    for (int mt = 0; mt < 2; mt++) {
        int co0 = coBase + wm * 32 + mt * 16 + r0;
        int co1 = co0 + 8;
#pragma unroll
        for (int nt = 0; nt < 8; nt++) {
            int n0 = nOff + wn * 64 + nt * 8 + cq;
            float4 d = acc[mt][nt];
            *(__half2*)&Mp[(size_t)co0 * NPAD + n0] = __floats2half2_rn(d.x, d.y);
            *(__half2*)&Mp[(size_t)co1 * NPAD + n0] = __floats2half2_rn(d.z, d.w);
        }
    }
}

// ---------------- 3) combine: A^T + BN/ReLU + y0/feas stores + fused GAP ----------------
__global__ void __launch_bounds__(256)
combine_kernel(const float* __restrict__ gma, const float* __restrict__ bta,
               const float* __restrict__ mu,  const float* __restrict__ var) {
    const int blk = blockIdx.x;          // ab*C + co
    const int co = blk & 255;
    const int ab = blk >> 8;
    const int a = ab >> 1, bb = ab & 1;

    float sc = 1.f, sh = 0.f;
    if (a > 0) {
        int br = a - 1;
        float vv = var[br * C_ + co];
        sc = gma[br * C_ + co] * rsqrtf(vv + 1e-5f);
        sh = bta[br * C_ + co] - mu[br * C_ + co] * sc;
    }

    const size_t MCP = (size_t)NA * B_ * C_ * NPAD;
    const size_t mbase = ((size_t)ab * C_ + co) * NPAD;
    const __half* M0p = g_M + 0 * MCP + mbase;
    const __half* M1p = g_M + 1 * MCP + mbase;
    const __half* M2p = g_M + 2 * MCP + mbase;
    const __half* M3p = g_M + 3 * MCP + mbase;

    __half* yp = (a == 0) ? &g_y0H[(size_t)(bb * C_ + co) * NPB] : nullptr;
    __half* fp = (a > 0) ? &g_feasH[(((size_t)(a - 1) * B_ + bb) * C_ + co) * NPB] : nullptr;

    float s = 0.f;
    const int TOTP = HO * 71;            // 10082 output pairs
    for (int pq = threadIdx.x; pq < TOTP; pq += 256) {
        int u = pq / 71, t = pq - u * 71;
        int np = u * VW + t;
        float M0 = __half2float(M0p[np]);
        float M1 = __half2float(M1p[np]);
        float M2 = __half2float(M2p[np]);
        float M3 = __half2float(M3p[np]);
        float o0 = M0 + M1 + M2;
        float o1 = M1 - M2 - M3;
        int p = u * WO + 2 * t;
        if (a == 0) {
            *(__half2*)&yp[p] = __floats2half2_rn(o0, o1);
        } else {
            float f0 = fmaxf(fmaf(o0, sc, sh), 0.f);
            float f1 = fmaxf(fmaf(o1, sc, sh), 0.f);
            *(__half2*)&fp[p] = __floats2half2_rn(f0, f1);
            s += f0 + f1;
        }
    }

    if (a > 0) {
        __shared__ float sm[256];
        sm[threadIdx.x] = s;
        __syncthreads();
        for (int st = 128; st > 0; st >>= 1) {
            if (threadIdx.x < st) sm[threadIdx.x] += sm[threadIdx.x + st];
            __syncthreads();
        }
        if (threadIdx.x == 0) atomicAdd(&g_fsum[bb * C_ + co], sm[0]);
    }
}

// ---------------- 4) attention ----------------
__global__ void __launch_bounds__(1024)
att_kernel(const float* __restrict__ fc1w, const float* __restrict__ fc1b,
           const float* __restrict__ fc2w, const float* __restrict__ fc2b) {
    extern __shared__ float sm[];
    float* sW1  = sm;
    float* sW2  = sm + 8192;
    float* sFs  = sm + 8192 + 32768;
    float* sZ   = sFs + 512;
    float* sAtt = sZ + 64;
    int t = threadIdx.x;

#pragma unroll
    for (int i = 0; i < 2; i++)
        ((float4*)sW1)[t + i * 1024] = ((const float4*)fc1w)[t + i * 1024];
#pragma unroll
    for (int i = 0; i < 8; i++) {
        int v4 = t + i * 1024;
        float4 w4 = ((const float4*)fc2w)[v4];
        int mc = v4 >> 3;
        int d0 = (v4 & 7) * 4;
        sW2[(d0 + 0) * 1024 + mc] = w4.x;
        sW2[(d0 + 1) * 1024 + mc] = w4.y;
        sW2[(d0 + 2) * 1024 + mc] = w4.z;
        sW2[(d0 + 3) * 1024 + mc] = w4.w;
    }
    if (t < B_ * C_) sFs[t] = g_fsum[t] * (1.f / (float)NPB);
    __syncthreads();

    {
        int pair = t >> 4;
        int b = pair >> 5, d = pair & 31;
        int sl = t & 15;
        float s = 0.f;
#pragma unroll
        for (int c = sl; c < C_; c += 16) s += sFs[b * C_ + c] * sW1[d * C_ + c];
        s += __shfl_down_sync(0xffffffffu, s, 8, 16);
        s += __shfl_down_sync(0xffffffffu, s, 4, 16);
        s += __shfl_down_sync(0xffffffffu, s, 2, 16);
        s += __shfl_down_sync(0xffffffffu, s, 1, 16);
        if (sl == 0) sZ[b * 32 + d] = s + fc1b[d];
    }
    __syncthreads();

#pragma unroll
    for (int i = 0; i < 2; i++) {
        int o = t + i * 1024;
        int b = o >> 10;
        int mc = o & 1023;
        float s = fc2b[mc];
#pragma unroll
        for (int d = 0; d < 32; d++) s += sZ[b * 32 + d] * sW2[d * 1024 + mc];
        sAtt[b * 1024 + mc] = s;
    }
    __syncthreads();

    if (t < B_ * C_) {
        int b = t >> 8, c = t & 255;
        float a0 = sAtt[b * 1024 + 0 * C_ + c];
        float a1 = sAtt[b * 1024 + 1 * C_ + c];
        float a2 = sAtt[b * 1024 + 2 * C_ + c];
        float a3 = sAtt[b * 1024 + 3 * C_ + c];
        float mx = fmaxf(fmaxf(a0, a1), fmaxf(a2, a3));
        float e0 = expf(a0 - mx), e1 = expf(a1 - mx), e2 = expf(a2 - mx), e3 = expf(a3 - mx);
        float inv = 1.f / (e0 + e1 + e2 + e3);
        g_att[(b * 4 + 0) * C_ + c] = e0 * inv;
        g_att[(b * 4 + 1) * C_ + c] = e1 * inv;
        g_att[(b * 4 + 2) * C_ + c] = e2 * inv;
        g_att[(b * 4 + 3) * C_ + c] = e3 * inv;
    }
}

// ---------------- 5) final blend ----------------
__global__ void final_kernel(float* __restrict__ out) {
    int idx = blockIdx.x * blockDim.x + threadIdx.x;
    const int total = B_ * C_ * NQ;
    if (idx >= total) return;
    int pq = idx % NQ;
    int bc = idx / NQ;
    int c  = bc % C_, b = bc / C_;

    uint2 yv = ((const uint2*)&g_y0H[(size_t)bc * NPB])[pq];
    float2 ylo = __half22float2(*(__half2*)&yv.x);
    float2 yhi = __half22float2(*(__half2*)&yv.y);
    float4 o = make_float4(ylo.x, ylo.y, yhi.x, yhi.y);
#pragma unroll
    for (int m = 0; m < 4; m++) {
        float wm = g_att[(b * 4 + m) * C_ + c];
        uint2 fv = ((const uint2*)&g_feasH[((size_t)m * B_ * C_ + bc) * NPB])[pq];
        float2 lo = __half22float2(*(__half2*)&fv.x);
        float2 hi = __half22float2(*(__half2*)&fv.y);
        o.x = fmaf(lo.x, wm, o.x);
        o.y = fmaf(lo.y, wm, o.y);
        o.z = fmaf(hi.x, wm, o.z);
        o.w = fmaf(hi.y, wm, o.w);
    }
    ((float4*)out)[idx] = o;
}

// ---------------- launch ----------------
extern "C" void kernel_launch(void* const* d_in, const int* in_sizes, int n_in,
                              void* d_out, int out_size) {
    const float* x    = (const float*)d_in[0];
    const float* w    = (const float*)d_in[1];
    const float* gma  = (const float*)d_in[2];
    const float* bta  = (const float*)d_in[3];
    const float* mu   = (const float*)d_in[4];
    const float* var  = (const float*)d_in[5];
    const float* fc1w = (const float*)d_in[6];
    const float* fc1b = (const float*)d_in[7];
    const float* fc2w = (const float*)d_in[8];
    const float* fc2b = (const float*)d_in[9];
    float* out = (float*)d_out;

    cudaFuncSetAttribute(gemm_wino_kernel,
                         cudaFuncAttributeMaxDynamicSharedMemorySize, SMEM_TOTAL);
    cudaFuncSetAttribute(att_kernel,
                         cudaFuncAttributeMaxDynamicSharedMemorySize, ATT_SMEM);

    prep_kernel<<<(C_ * KW + 255) / 256, 256>>>(w);

    dim3 sgrid(81, C_, NA * B_);
    sampleV_kernel<<<sgrid, 64>>>(x);

    dim3 ggrid(2 * NT, NA * B_, 4);
    gemm_wino_kernel<<<ggrid, 256, SMEM_TOTAL>>>();

    combine_kernel<<<NA * B_ * C_, 256>>>(gma, bta, mu, var);

    att_kernel<<<1, 1024, ATT_SMEM>>>(fc1w, fc1b, fc2w, fc2b);
    final_kernel<<<(B_ * C_ * NQ + 255) / 256, 256>>>(out);
}

// round 12
// speedup vs baseline: 1.2729x; 1.0246x over previous
#include <cuda_runtime.h>
#include <cuda_fp16.h>
#include <cstdint>

// ---------------- problem constants ----------------
constexpr int B_   = 2;
constexpr int C_   = 256;
constexpr int Hh   = 48;
constexpr int Ww   = 48;
constexpr int H3   = 144;
constexpr int HO   = 142, WO = 142;
constexpr int NPB  = HO * WO;        // 20164
constexpr int NA   = 5;

// Winograd F(2,3) along v: 4 components, K = C*3
constexpr int KW   = C_ * 3;         // 768
constexpr int VW   = 72;             // V row width (71 valid tiles + 1 pad)
constexpr int PLV  = H3 * VW;        // 10368
constexpr size_t CPSTR = (size_t)NA * B_ * C_ * PLV;
constexpr int PADE = 8192;

// GEMM tiling: 128co x 128n, CHUNK 32, 4 stages (r9-proven shape)
constexpr int NPAD  = 10240;         // 80 tiles * 128
constexpr int NT    = 80;
constexpr int CHUNK = 32;
constexpr int NCH   = KW / CHUNK;    // 24
constexpr int NS    = 4;
constexpr int AROWB = 80;
constexpr int BROWB = 272;
constexpr int OFF_B = 128 * AROWB;                 // 10240
constexpr int STAGE = OFF_B + 32 * BROWB;          // 18944
constexpr int SMEM_TOTAL = NS * STAGE;             // 75776

constexpr int ATT_SMEM = (8192 + 32768 + 512 + 64 + 2048) * 4;  // 174336

// vector-iteration space over M planes: 142 rows x 18 quads (4 tiles each)
constexpr int NITER = HO * 18;       // 2556

// ---------------- static scratch ----------------
__device__ __align__(16) unsigned short g_v[4 * CPSTR + PADE];
__device__ __align__(16) unsigned short g_wU[4 * C_ * KW];
__device__ __align__(16) __half g_M[(size_t)4 * NA * B_ * C_ * NPAD];
__device__ float g_fsum[B_ * C_];
__device__ float g_att[B_ * 4 * C_];

// ---------------- angle offset tables ----------------
#define S2  1.4142135623730951
#define S2H 0.7071067811865476
__constant__ float c_ox[45] = {
    0.f,0.f,0.f,0.f,0.f,0.f,0.f,0.f,0.f,
    (float)(1.0-S2), (float)(1.0-S2H), 1.f, (float)(-S2H), 0.f, (float)(S2H),
    -1.f, (float)(S2H-1.0), (float)(S2-1.0),
    0.f,1.f,2.f,-1.f,0.f,1.f,-2.f,-1.f,0.f,
    1.f, (float)(1.0+S2H), (float)(1.0+S2), (float)(-S2H), 0.f, (float)(S2H),
    (float)(-1.0-S2), (float)(-1.0-S2H), -1.f,
    2.f,2.f,2.f,0.f,0.f,0.f,-2.f,-2.f,-2.f
};
__constant__ float c_oy[45] = {
    0.f,0.f,0.f,0.f,0.f,0.f,0.f,0.f,0.f,
    1.f, (float)(S2H), (float)(S2-1.0), (float)(1.0-S2H), 0.f, (float)(S2H-1.0),
    (float)(1.0-S2), (float)(-S2H), -1.f,
    2.f,1.f,0.f,1.f,0.f,-1.f,0.f,-1.f,-2.f,
    (float)(1.0+S2), (float)(S2H), -1.f, (float)(1.0+S2H), 0.f, (float)(-1.0-S2H),
    1.f, (float)(-S2H), (float)(1.0+S2),
    2.f,0.f,-2.f,2.f,0.f,-2.f,2.f,0.f,-2.f
};
__constant__ int c_oxi[27] = {
    0,0,0,0,0,0,0,0,0,
    0,1,2,-1,0,1,-2,-1,0,
    2,2,2,0,0,0,-2,-2,-2
};
__constant__ int c_oyi[27] = {
    0,0,0,0,0,0,0,0,0,
    2,1,0,1,0,-1,0,-1,-2,
    2,0,-2,2,0,-2,2,0,-2
};

// ---------------- helpers ----------------
__device__ __forceinline__ uint32_t smem_u32(const void* p) {
    uint32_t a;
    asm("{ .reg .u64 t; cvta.to.shared.u64 t, %1; cvt.u32.u64 %0, t; }" : "=r"(a) : "l"(p));
    return a;
}
__device__ __forceinline__ void cpasync16(uint32_t dst, const void* src) {
    asm volatile("cp.async.cg.shared.global [%0], [%1], 16;" :: "r"(dst), "l"(src));
}
__device__ __forceinline__ void cp_commit() {
    asm volatile("cp.async.commit_group;" ::: "memory");
}
__device__ __forceinline__ void cp_wait2() {
    asm volatile("cp.async.wait_group %0;" :: "n"(2) : "memory");
}
__device__ __forceinline__ void ldmx4(uint32_t* r, uint32_t addr) {
    asm volatile("ldmatrix.sync.aligned.m8n8.x4.shared.b16 {%0,%1,%2,%3}, [%4];"
                 : "=r"(r[0]), "=r"(r[1]), "=r"(r[2]), "=r"(r[3]) : "r"(addr));
}
__device__ __forceinline__ void ldmx4t(uint32_t* r, uint32_t addr) {
    asm volatile("ldmatrix.sync.aligned.m8n8.x4.trans.shared.b16 {%0,%1,%2,%3}, [%4];"
                 : "=r"(r[0]), "=r"(r[1]), "=r"(r[2]), "=r"(r[3]) : "r"(addr));
}
__device__ __forceinline__ void mma_fp16(float4& d, const uint32_t a[4], uint32_t b0, uint32_t b1) {
    asm volatile("mma.sync.aligned.m16n8k16.row.col.f32.f16.f16.f32 "
                 "{%0,%1,%2,%3}, {%4,%5,%6,%7}, {%8,%9}, {%0,%1,%2,%3};"
                 : "+f"(d.x), "+f"(d.y), "+f"(d.z), "+f"(d.w)
                 : "r"(a[0]), "r"(a[1]), "r"(a[2]), "r"(a[3]), "r"(b0), "r"(b1));
}
// unpack uint2 (4 fp16) to 4 floats
__device__ __forceinline__ void up4(uint2 v, float* f) {
    float2 lo = __half22float2(*(__half2*)&v.x);
    float2 hi = __half22float2(*(__half2*)&v.y);
    f[0] = lo.x; f[1] = lo.y; f[2] = hi.x; f[3] = hi.y;
}

// ---------------- 0) prep: weight winograd transform ----------------
__global__ void prep_kernel(const float* __restrict__ w) {
    int i = blockIdx.x * blockDim.x + threadIdx.x;
    if (i >= C_ * KW) return;
    int co = i / KW;
    int k  = i - co * KW;          // ci*3 + ki
    int ci = k / 3, ki = k - ci * 3;
    const float* gp = w + (((size_t)co * C_ + ci) * 3 + ki) * 3;
    float g0 = gp[0], g1 = gp[1], g2 = gp[2];
    g_wU[(0 * C_ + co) * KW + k] = __half_as_ushort(__float2half_rn(g0));
    g_wU[(1 * C_ + co) * KW + k] = __half_as_ushort(__float2half_rn(0.5f * (g0 + g1 + g2)));
    g_wU[(2 * C_ + co) * KW + k] = __half_as_ushort(__float2half_rn(0.5f * (g0 - g1 + g2)));
    g_wU[(3 * C_ + co) * KW + k] = __half_as_ushort(__float2half_rn(g2));
}

// ---------------- 1) fused bilinear resample + V transform ----------------
__global__ void sampleV_kernel(const float* __restrict__ x) {
    int ip = blockIdx.x * 64 + threadIdx.x;    // [0, 5184) = 144 rows * 36 tile-pairs
    int c  = blockIdx.y;
    int ab = blockIdx.z;                        // a*2 + bb
    int a  = ab >> 1, bb = ab & 1;

    int r  = ip / 36;
    int tp = ip - r * 36;

    int i = r / 3, ki = r - i * 3;
    const float* xp = x + (bb * C_ + c) * (Hh * Ww);

    float s[6];
    int jmax = (tp == 35) ? 4 : 6;
    for (int j = 0; j < 6; j++) {
        if (j >= jmax) { s[j] = 0.f; continue; }
        int cc = 4 * tp + j;
        int jj = cc / 3, kj = cc - jj * 3;
        int k9 = ki * 3 + kj;
        float v;
        if ((a & 1) == 0) {
            int ia = a >> 1;
            int px = i + ki + c_oxi[ia * 9 + k9];
            int py = jj + kj + c_oyi[ia * 9 + k9];
            v = (px >= 1 && px <= Hh && py >= 1 && py <= Ww)
                ? xp[(px - 1) * Ww + (py - 1)] : 0.f;
        } else {
            float sx = (float)(ki - 1) + c_ox[a * 9 + k9];
            float sy = (float)(kj - 1) + c_oy[a * 9 + k9];
            float px = (float)(i + 1) + sx;
            float py = (float)(jj + 1) + sy;
            float fx = floorf(px), fy = floorf(py);
            const float HI = 49.f;
            float ltx = fminf(fmaxf(fx,       0.f), HI);
            float lty = fminf(fmaxf(fy,       0.f), HI);
            float rbx = fminf(fmaxf(fx + 1.f, 0.f), HI);
            float rby = fminf(fmaxf(fy + 1.f, 0.f), HI);
            float pxc = fminf(fmaxf(px,       0.f), HI);
            float pyc = fminf(fmaxf(py,       0.f), HI);
            float g_lt = (1.f + (ltx - pxc)) * (1.f + (lty - pyc));
            float g_rb = (1.f - (rbx - pxc)) * (1.f - (rby - pyc));
            float g_lb = (1.f + (ltx - pxc)) * (1.f - (rby - pyc));
            float g_rt = (1.f - (rbx - pxc)) * (1.f + (lty - pyc));
            int ix0 = (int)ltx, iy0 = (int)lty, ix1 = (int)rbx, iy1 = (int)rby;
            auto gat = [&](int ix, int iy) -> float {
                ix -= 1; iy -= 1;
                if (ix < 0 || ix >= Hh || iy < 0 || iy >= Ww) return 0.f;
                return xp[ix * Ww + iy];
            };
            v = g_lt * gat(ix0, iy0) + g_rb * gat(ix1, iy1)
              + g_lb * gat(ix0, iy1) + g_rt * gat(ix1, iy0);
        }
        s[j] = v;
    }

    float v0[4] = { s[0] - s[2], s[1] + s[2], s[2] - s[1], s[1] - s[3] };
    float v1[4];
    if (tp == 35) { v1[0] = v1[1] = v1[2] = v1[3] = 0.f; }
    else {
        v1[0] = s[2] - s[4]; v1[1] = s[3] + s[4];
        v1[2] = s[4] - s[3]; v1[3] = s[3] - s[5];
    }

    size_t base = ((size_t)ab * C_ + c) * PLV + r * VW + 2 * tp;
#pragma unroll
    for (int cp = 0; cp < 4; cp++) {
        uint32_t pk = (uint32_t)__half_as_ushort(__float2half_rn(v0[cp]))
                    | ((uint32_t)__half_as_ushort(__float2half_rn(v1[cp])) << 16);
        *(uint32_t*)&g_v[(size_t)cp * CPSTR + base] = pk;
    }
}

// ---------------- 2) wino GEMM: comp per blockIdx.z, r9 pipeline ----------------
__global__ void __launch_bounds__(256)
gemm_wino_kernel() {
    extern __shared__ char smem[];
    const uint32_t sb = smem_u32(smem);
    const int tid = threadIdx.x;
    const int cp  = blockIdx.z;
    const int ab  = blockIdx.y;
    const int coBase = (blockIdx.x & 1) * 128;
    const int nOff   = (blockIdx.x >> 1) * 128;
    const int lane = tid & 31, wid = tid >> 5;
    const int wm = wid & 3, wn = wid >> 2;

    const int aRow = tid >> 2, aPc = tid & 3;
    const int bRow = tid >> 4, bPc = tid & 15;

    const size_t vBase = (size_t)cp * CPSTR + (size_t)ab * C_ * PLV;

    auto issueChunk = [&](int ch, int st) {
        const uint32_t sg = sb + (uint32_t)st * STAGE;
#pragma unroll
        for (int t2 = 0; t2 < 2; t2++) {
            int row = aRow + t2 * 64;
            const char* src = (const char*)g_wU
                + ((size_t)(cp * C_ + coBase + row) * KW + (size_t)ch * CHUNK) * 2 + aPc * 16;
            cpasync16(sg + row * AROWB + aPc * 16, src);
        }
#pragma unroll
        for (int t2 = 0; t2 < 2; t2++) {
            int row = bRow + t2 * 16;
            int k  = ch * CHUNK + row;
            int ci = k / 3;
            int ki = k - ci * 3;
            const char* src = (const char*)g_v
                + (vBase + (size_t)ci * PLV + ki * VW + nOff) * 2 + bPc * 16;
            cpasync16(sg + OFF_B + row * BROWB + bPc * 16, src);
        }
    };

    float4 acc[2][8];
#pragma unroll
    for (int i = 0; i < 2; i++)
#pragma unroll
        for (int j = 0; j < 8; j++) acc[i][j] = make_float4(0.f, 0.f, 0.f, 0.f);

    const uint32_t aLd = (uint32_t)(wm * 32 + (lane & 15)) * AROWB + (uint32_t)(lane >> 4) * 16;
    const uint32_t bLd0 = (uint32_t)(lane & 15) * BROWB
                        + (uint32_t)(wn * 64 + (lane >> 4) * 8) * 2;

    auto computeStage = [&](int st) {
        const uint32_t sg = sb + (uint32_t)st * STAGE;
#pragma unroll
        for (int ks = 0; ks < 2; ks++) {
            uint32_t aH[2][4], bV[4][4];
#pragma unroll
            for (int mt = 0; mt < 2; mt++)
                ldmx4(aH[mt], sg + aLd + (uint32_t)(mt * 16) * AROWB + ks * 32);
#pragma unroll
            for (int bt = 0; bt < 4; bt++)
                ldmx4t(bV[bt], sg + OFF_B + bLd0 + (uint32_t)(ks * 16) * BROWB + (uint32_t)(bt * 16) * 2);
#pragma unroll
            for (int mt = 0; mt < 2; mt++)
#pragma unroll
                for (int nt = 0; nt < 8; nt++) {
                    uint32_t b0 = bV[nt >> 1][(nt & 1) * 2], b1 = bV[nt >> 1][(nt & 1) * 2 + 1];
                    mma_fp16(acc[mt][nt], aH[mt], b0, b1);
                }
        }
    };

#pragma unroll
    for (int s = 0; s < NS - 1; s++) { issueChunk(s, s); cp_commit(); }

    for (int ch = 0; ch < NCH; ch++) {
        cp_wait2();
        __syncthreads();
        if (ch + NS - 1 < NCH) issueChunk(ch + NS - 1, (ch + NS - 1) & (NS - 1));
        cp_commit();
        computeStage(ch & (NS - 1));
    }

    const int r0 = lane >> 2;
    const int cq = (lane & 3) * 2;
    __half* Mp = g_M + (size_t)(cp * NA * B_ + ab) * ((size_t)C_ * NPAD);
#pragma unroll
    for (int mt = 0; mt < 2; mt++) {
        int co0 = coBase + wm * 32 + mt * 16 + r0;
        int co1 = co0 + 8;
#pragma unroll
        for (int nt = 0; nt < 8; nt++) {
            int n0 = nOff + wn * 64 + nt * 8 + cq;
            float4 d = acc[mt][nt];
            *(__half2*)&Mp[(size_t)co0 * NPAD + n0] = __floats2half2_rn(d.x, d.y);
            *(__half2*)&Mp[(size_t)co1 * NPAD + n0] = __floats2half2_rn(d.z, d.w);
        }
    }
}

// ---------------- 3) GAP directly from M (a=1..4), vectorized, no atomics ----------------
__global__ void __launch_bounds__(256)
gap_kernel(const float* __restrict__ gma, const float* __restrict__ bta,
           const float* __restrict__ mu,  const float* __restrict__ var) {
    const int blk = blockIdx.x;          // bb*C + co
    const int co = blk & 255;
    const int bb = blk >> 8;

    float sc[4], sh[4];
#pragma unroll
    for (int br = 0; br < 4; br++) {
        float vv = var[br * C_ + co];
        sc[br] = gma[br * C_ + co] * rsqrtf(vv + 1e-5f);
        sh[br] = bta[br * C_ + co] - mu[br * C_ + co] * sc[br];
    }

    const size_t MCP = (size_t)NA * B_ * C_ * NPAD;
    const __half* mp[4][4];              // [a-1][cp]
#pragma unroll
    for (int br = 0; br < 4; br++)
#pragma unroll
        for (int cpp = 0; cpp < 4; cpp++)
            mp[br][cpp] = g_M + (size_t)cpp * MCP
                        + (((size_t)((br + 1) * 2 + bb) * C_ + co) * NPAD);

    float s = 0.f;
    for (int i = threadIdx.x; i < NITER; i += 256) {
        int u = i / 18, q = i - u * 18;
        int np = u * VW + 4 * q;
        bool full = (q != 17);
#pragma unroll
        for (int br = 0; br < 4; br++) {
            float M0[4], M1[4], M2[4], M3[4];
            up4(*(const uint2*)&mp[br][0][np], M0);
            up4(*(const uint2*)&mp[br][1][np], M1);
            up4(*(const uint2*)&mp[br][2][np], M2);
            up4(*(const uint2*)&mp[br][3][np], M3);
#pragma unroll
            for (int j = 0; j < 4; j++) {
                if (j == 3 && !full) continue;
                float o0 = M0[j] + M1[j] + M2[j];
                float o1 = M1[j] - M2[j] - M3[j];
                s += fmaxf(fmaf(o0, sc[br], sh[br]), 0.f)
                   + fmaxf(fmaf(o1, sc[br], sh[br]), 0.f);
            }
        }
    }

    __shared__ float sm[256];
    sm[threadIdx.x] = s;
    __syncthreads();
    for (int st = 128; st > 0; st >>= 1) {
        if (threadIdx.x < st) sm[threadIdx.x] += sm[threadIdx.x + st];
        __syncthreads();
    }
    if (threadIdx.x == 0) g_fsum[bb * C_ + co] = sm[0];
}

// ---------------- 4) attention ----------------
__global__ void __launch_bounds__(1024)
att_kernel(const float* __restrict__ fc1w, const float* __restrict__ fc1b,
           const float* __restrict__ fc2w, const float* __restrict__ fc2b) {
    extern __shared__ float sm[];
    float* sW1  = sm;
    float* sW2  = sm + 8192;
    float* sFs  = sm + 8192 + 32768;
    float* sZ   = sFs + 512;
    float* sAtt = sZ + 64;
    int t = threadIdx.x;

#pragma unroll
    for (int i = 0; i < 2; i++)
        ((float4*)sW1)[t + i * 1024] = ((const float4*)fc1w)[t + i * 1024];
#pragma unroll
    for (int i = 0; i < 8; i++) {
        int v4 = t + i * 1024;
        float4 w4 = ((const float4*)fc2w)[v4];
        int mc = v4 >> 3;
        int d0 = (v4 & 7) * 4;
        sW2[(d0 + 0) * 1024 + mc] = w4.x;
        sW2[(d0 + 1) * 1024 + mc] = w4.y;
        sW2[(d0 + 2) * 1024 + mc] = w4.z;
        sW2[(d0 + 3) * 1024 + mc] = w4.w;
    }
    if (t < B_ * C_) sFs[t] = g_fsum[t] * (1.f / (float)NPB);
    __syncthreads();

    {
        int pair = t >> 4;
        int b = pair >> 5, d = pair & 31;
        int sl = t & 15;
        float s = 0.f;
#pragma unroll
        for (int c = sl; c < C_; c += 16) s += sFs[b * C_ + c] * sW1[d * C_ + c];
        s += __shfl_down_sync(0xffffffffu, s, 8, 16);
        s += __shfl_down_sync(0xffffffffu, s, 4, 16);
        s += __shfl_down_sync(0xffffffffu, s, 2, 16);
        s += __shfl_down_sync(0xffffffffu, s, 1, 16);
        if (sl == 0) sZ[b * 32 + d] = s + fc1b[d];
    }
    __syncthreads();

#pragma unroll
    for (int i = 0; i < 2; i++) {
        int o = t + i * 1024;
        int b = o >> 10;
        int mc = o & 1023;
        float s = fc2b[mc];
#pragma unroll
        for (int d = 0; d < 32; d++) s += sZ[b * 32 + d] * sW2[d * 1024 + mc];
        sAtt[b * 1024 + mc] = s;
    }
    __syncthreads();

    if (t < B_ * C_) {
        int b = t >> 8, c = t & 255;
        float a0 = sAtt[b * 1024 + 0 * C_ + c];
        float a1 = sAtt[b * 1024 + 1 * C_ + c];
        float a2 = sAtt[b * 1024 + 2 * C_ + c];
        float a3 = sAtt[b * 1024 + 3 * C_ + c];
        float mx = fmaxf(fmaxf(a0, a1), fmaxf(a2, a3));
        float e0 = expf(a0 - mx), e1 = expf(a1 - mx), e2 = expf(a2 - mx), e3 = expf(a3 - mx);
        float inv = 1.f / (e0 + e1 + e2 + e3);
        g_att[(b * 4 + 0) * C_ + c] = e0 * inv;
        g_att[(b * 4 + 1) * C_ + c] = e1 * inv;
        g_att[(b * 4 + 2) * C_ + c] = e2 * inv;
        g_att[(b * 4 + 3) * C_ + c] = e3 * inv;
    }
}

// ---------------- 5) final: A^T + BN/ReLU + blend, straight from M ----------------
__global__ void __launch_bounds__(256)
final_kernel(const float* __restrict__ gma, const float* __restrict__ bta,
             const float* __restrict__ mu,  const float* __restrict__ var,
             float* __restrict__ out) {
    const int blk = blockIdx.x;          // bb*C + co
    const int co = blk & 255;
    const int bb = blk >> 8;

    float sc[4], sh[4], aw[4];
#pragma unroll
    for (int br = 0; br < 4; br++) {
        float vv = var[br * C_ + co];
        sc[br] = gma[br * C_ + co] * rsqrtf(vv + 1e-5f);
        sh[br] = bta[br * C_ + co] - mu[br * C_ + co] * sc[br];
        aw[br] = g_att[(bb * 4 + br) * C_ + co];
    }

    const size_t MCP = (size_t)NA * B_ * C_ * NPAD;
    const __half* mp[5][4];              // [a][cp]
#pragma unroll
    for (int a = 0; a < 5; a++)
#pragma unroll
        for (int cpp = 0; cpp < 4; cpp++)
            mp[a][cpp] = g_M + (size_t)cpp * MCP
                       + (((size_t)(a * 2 + bb) * C_ + co) * NPAD);

    float* op = out + (size_t)(bb * C_ + co) * NPB;

    for (int i = threadIdx.x; i < NITER; i += 256) {
        int u = i / 18, q = i - u * 18;
        int np = u * VW + 4 * q;
        bool full = (q != 17);

        float acc0[4], acc1[4];
        {   // a = 0: identity branch
            float M0[4], M1[4], M2[4], M3[4];
            up4(*(const uint2*)&mp[0][0][np], M0);
            up4(*(const uint2*)&mp[0][1][np], M1);
            up4(*(const uint2*)&mp[0][2][np], M2);
            up4(*(const uint2*)&mp[0][3][np], M3);
#pragma unroll
            for (int j = 0; j < 4; j++) {
                acc0[j] = M0[j] + M1[j] + M2[j];
                acc1[j] = M1[j] - M2[j] - M3[j];
            }
        }
#pragma unroll
        for (int br = 0; br < 4; br++) {
            float M0[4], M1[4], M2[4], M3[4];
            up4(*(const uint2*)&mp[br + 1][0][np], M0);
            up4(*(const uint2*)&mp[br + 1][1][np], M1);
            up4(*(const uint2*)&mp[br + 1][2][np], M2);
            up4(*(const uint2*)&mp[br + 1][3][np], M3);
#pragma unroll
            for (int j = 0; j < 4; j++) {
                float o0 = M0[j] + M1[j] + M2[j];
                float o1 = M1[j] - M2[j] - M3[j];
                float f0 = fmaxf(fmaf(o0, sc[br], sh[br]), 0.f);
                float f1 = fmaxf(fmaf(o1, sc[br], sh[br]), 0.f);
                acc0[j] = fmaf(f0, aw[br], acc0[j]);
                acc1[j] = fmaf(f1, aw[br], acc1[j]);
            }
        }
        int p = u * WO + 8 * q;
#pragma unroll
        for (int j = 0; j < 4; j++) {
            if (j == 3 && !full) continue;
            *(float2*)&op[p + 2 * j] = make_float2(acc0[j], acc1[j]);
        }
    }
}

// ---------------- launch ----------------
extern "C" void kernel_launch(void* const* d_in, const int* in_sizes, int n_in,
                              void* d_out, int out_size) {
    const float* x    = (const float*)d_in[0];
    const float* w    = (const float*)d_in[1];
    const float* gma  = (const float*)d_in[2];
    const float* bta  = (const float*)d_in[3];
    const float* mu   = (const float*)d_in[4];
    const float* var  = (const float*)d_in[5];
    const float* fc1w = (const float*)d_in[6];
    const float* fc1b = (const float*)d_in[7];
    const float* fc2w = (const float*)d_in[8];
    const float* fc2b = (const float*)d_in[9];
    float* out = (float*)d_out;

    cudaFuncSetAttribute(gemm_wino_kernel,
                         cudaFuncAttributeMaxDynamicSharedMemorySize, SMEM_TOTAL);
    cudaFuncSetAttribute(att_kernel,
                         cudaFuncAttributeMaxDynamicSharedMemorySize, ATT_SMEM);

    prep_kernel<<<(C_ * KW + 255) / 256, 256>>>(w);

    dim3 sgrid(81, C_, NA * B_);
    sampleV_kernel<<<sgrid, 64>>>(x);

    dim3 ggrid(2 * NT, NA * B_, 4);
    gemm_wino_kernel<<<ggrid, 256, SMEM_TOTAL>>>();

    gap_kernel<<<B_ * C_, 256>>>(gma, bta, mu, var);
    att_kernel<<<1, 1024, ATT_SMEM>>>(fc1w, fc1b, fc2w, fc2b);
    final_kernel<<<B_ * C_, 256>>>(gma, bta, mu, var, out);
}